// round 6
// baseline (speedup 1.0000x reference)
#include <cuda_runtime.h>
#include <cuda_fp16.h>
#include <cstdint>

typedef unsigned long long u64;

#define NQ 16384
#define NB 128
#define NF 64
#define HD 128
#define EPSF 1e-8f

#define THREADS 640
#define WARPS_PER_CTA 20
#define PAIRS_PER_CTA 10
#define MAXQ 11

// Half-precision packed probe table (prep output), 16B per (f,p):
// [Pr_p, Pr_p+64, Pi_p, Pi_p+64, w_p, w_p+64, mw_p, mw_p+64]  (8 halves)
__device__ __half g_probeH[NF * 64 * 8];

// ---------- helpers ----------
__device__ __forceinline__ u64 f2pk(float lo, float hi) {
    u64 r; asm("mov.b64 %0, {%1,%2};" : "=l"(r) : "f"(lo), "f"(hi)); return r;
}
__device__ __forceinline__ void f2upk(float& lo, float& hi, u64 v) {
    asm("mov.b64 {%0,%1}, %2;" : "=f"(lo), "=f"(hi) : "l"(v));
}
__device__ __forceinline__ u64 f2add(u64 a, u64 b) {
    u64 d; asm("add.rn.f32x2 %0, %1, %2;" : "=l"(d) : "l"(a), "l"(b)); return d;
}
__device__ __forceinline__ u64 f2fma(u64 a, u64 b, u64 c) {
    u64 d; asm("fma.rn.f32x2 %0, %1, %2, %3;" : "=l"(d) : "l"(a), "l"(b), "l"(c)); return d;
}
__device__ __forceinline__ float sqrt_apx(float x) {
    float r; asm("sqrt.approx.f32 %0, %1;" : "=f"(r) : "f"(x)); return r;
}
__device__ __forceinline__ float rcp_apx(float x) {
    float r; asm("rcp.approx.f32 %0, %1;" : "=f"(r) : "f"(x)); return r;
}
__device__ __forceinline__ uint32_t su32(const void* p) {
    uint32_t a;
    asm("{ .reg .u64 t; cvta.to.shared.u64 t, %1; cvt.u32.u64 %0, t; }"
        : "=r"(a) : "l"(p));
    return a;
}
__device__ __forceinline__ u64 h2_to_f2(uint32_t h2bits) {
    __half2 h = *reinterpret_cast<__half2*>(&h2bits);
    float2 f = __half22float2(h);
    return f2pk(f.x, f.y);
}

// ---------- prep: one block per probe b, one thread per f ----------
__global__ __launch_bounds__(64)
void prep_kernel(const float* __restrict__ probes,
                 const float* __restrict__ angles,
                 const float* __restrict__ qw,
                 const float* __restrict__ qmw) {
    __shared__ float red[2];
    const int b = blockIdx.x;   // 0..127
    const int f = threadIdx.x;  // 0..63
    const int warp = f >> 5;
    const int lane = f & 31;

    float x0 = probes[b * HD + f];
    float x1 = probes[b * HD + NF + f];
    float ss = fmaf(x0, x0, x1 * x1);
#pragma unroll
    for (int o = 16; o; o >>= 1) ss += __shfl_xor_sync(0xffffffffu, ss, o);
    if (lane == 0) red[warp] = ss;
    __syncthreads();
    float inv = 1.0f / (sqrtf(red[0] + red[1]) + EPSF);

    float pr = x0 * inv;
    float pi = x1 * inv;
    float c, s;
    sincosf(angles[f], &s, &c);
    float Pr = pr * c - pi * s;
    float Pi = pr * s + pi * c;
    float xw = qw[b * NF + f];
    float sp = (xw > 20.0f) ? xw : log1pf(expf(xw));
    float w = -sp;
    float mw = qmw[b * NF + f];

    int p = b & 63;
    int hi = b >> 6;
    int base = (f * 64 + p) * 8;
    g_probeH[base + 0 + hi] = __float2half_rn(Pr);
    g_probeH[base + 2 + hi] = __float2half_rn(Pi);
    g_probeH[base + 4 + hi] = __float2half_rn(w);
    g_probeH[base + 6 + hi] = __float2half_rn(mw);
}

// ---------- SMEM layout (float offsets) ----------
#define OFF_SH  0                               // probe half table: 16384 floats (64KB)
#define OFF_QT  16384                           // q-tables: 10 pairs * 11q * 64f * 4 = 28160 floats (110KB)
#define OFF_QN  44544                           // per-warp qn scratch: 20*128 = 2560 floats (10KB)
#define SMEM_FLOATS 47104                       // 184 KB

// f-loop over a batch of JN q's. Warp handles 32 b-pairs (p = lane + 32*h).
template<int JN>
__device__ __forceinline__ void run_batch(uint32_t aP, uint32_t aQT,
                                          u64 biasp, u64 EPS2,
                                          float* __restrict__ out, int q0, int p) {
    u64 acc[JN];
#pragma unroll
    for (int j = 0; j < JN; j++) acc[j] = biasp;

#pragma unroll 2
    for (int f = 0; f < NF; f++) {
        const uint32_t fo = (uint32_t)f * 1024u;
        u64 vlo, vhi;
        asm("ld.shared.v2.b64 {%0,%1}, [%2];" : "=l"(vlo), "=l"(vhi) : "r"(aP + fo));
        uint32_t u0, u1, u2, u3;
        asm("mov.b64 {%0,%1}, %2;" : "=r"(u0), "=r"(u1) : "l"(vlo));
        asm("mov.b64 {%0,%1}, %2;" : "=r"(u2), "=r"(u3) : "l"(vhi));
        const u64 Pr = h2_to_f2(u0);
        const u64 Pi = h2_to_f2(u1);
        const u64 w  = h2_to_f2(u2);
        const u64 mw = h2_to_f2(u3);

#pragma unroll
        for (int j = 0; j < JN; j++) {
            float tx, ty, tz, tw_;
            asm("ld.shared.v4.f32 {%0,%1,%2,%3}, [%4];"
                : "=f"(tx), "=f"(ty), "=f"(tz), "=f"(tw_)
                : "r"(aQT + (uint32_t)j * 1024u + (uint32_t)f * 16u));
            u64 nqr = f2pk(tx, tx);
            u64 nqi = f2pk(ty, ty);
            u64 qm2 = f2pk(tz, tz);
            u64 er = f2add(Pr, nqr);
            u64 ei = f2add(Pi, nqi);
            u64 d2 = f2fma(er, er, f2fma(ei, ei, EPS2));
            float lo, hi; f2upk(lo, hi, d2);
            u64 dist = f2pk(sqrt_apx(lo), sqrt_apx(hi));
            acc[j] = f2fma(dist, w, acc[j]);
            acc[j] = f2fma(qm2, mw, acc[j]);
        }
    }

#pragma unroll
    for (int j = 0; j < JN; j++) {
        float o0, o1; f2upk(o0, o1, acc[j]);
        float* orow = out + (size_t)(q0 + j) * NB;
        orow[p]      = o0;
        orow[p + 64] = o1;
    }
}

__global__ __launch_bounds__(THREADS, 1)
void main_kernel(const float* __restrict__ Q,
                 const float* __restrict__ bias,
                 float* __restrict__ out) {
    extern __shared__ float sm[];
    const int tid  = threadIdx.x;
    const int warp = tid >> 5;
    const int lane = tid & 31;
    const int pid  = warp >> 1;     // pair id 0..9
    const int h    = warp & 1;      // warp half within pair
    const int p    = lane + 32 * h; // b-pair index 0..63

    // Stage half probe table into SMEM (64KB = 4096 float4)
    {
        const float4* gH = (const float4*)g_probeH;
        float4* sH4 = (float4*)(sm + OFF_SH);
        for (int i = tid; i < NF * 64 * 8 / 8; i += THREADS)
            sH4[i] = gH[i];
    }

    const u64 biasp = f2pk(bias[p], bias[p + 64]);
    const u64 EPS2  = f2pk(EPSF, EPSF);

    __syncthreads();

    const uint32_t sbase = su32(sm);
    const uint32_t aP  = sbase + (uint32_t)p * 16u;                        // probe row for pair p
    const uint32_t aQT = sbase + (uint32_t)OFF_QT * 4u + (uint32_t)pid * (MAXQ * 64u * 16u);
    float*  qn = sm + OFF_QN + warp * 128;
    float4* qt = (float4*)(sm + OFF_QT + pid * MAXQ * 64 * 4);

    // ---- contiguous q-range assignment per warp-pair (balanced to +/-1 q) ----
    const int npairs = gridDim.x * PAIRS_PER_CTA;
    const int gp = blockIdx.x * PAIRS_PER_CTA + pid;
    const int per = NQ / npairs;
    const int rem = NQ % npairs;
    int cnt, q0;
    if (gp < rem) { cnt = per + 1; q0 = gp * (per + 1); }
    else          { cnt = per;     q0 = rem * (per + 1) + (gp - rem) * per; }

    while (cnt > 0) {
        const int jn = (cnt > MAXQ) ? MAXQ : cnt;

        // ---- batch prep: warps of the pair split the q's by parity of j ----
        for (int j = h; j < jn; j += 2) {
            const float4* Qv = (const float4*)(Q + (size_t)(q0 + j) * HD);
            float4 v = Qv[lane];
            float ss = fmaf(v.x, v.x, fmaf(v.y, v.y, fmaf(v.z, v.z, v.w * v.w)));
#pragma unroll
            for (int o = 16; o; o >>= 1) ss += __shfl_xor_sync(0xffffffffu, ss, o);
            float inv = rcp_apx(sqrt_apx(ss) + EPSF);
            ((float4*)qn)[lane] = make_float4(v.x * inv, v.y * inv, v.z * inv, v.w * inv);
            __syncwarp();
#pragma unroll
            for (int k = 0; k < 2; k++) {
                int f = lane + k * 32;
                float qr = qn[f];
                float qi = qn[f + 64];
                float qm = sqrt_apx(fmaf(qr, qr, fmaf(qi, qi, EPSF)));
                qt[j * 64 + f] = make_float4(-qr, -qi, qm, 0.0f);
            }
            __syncwarp();
        }
        // pair-scoped named barrier (ids 1..10)
        asm volatile("bar.sync %0, %1;" :: "r"(pid + 1), "r"(64) : "memory");

        switch (jn) {
            case 11: run_batch<11>(aP, aQT, biasp, EPS2, out, q0, p); break;
            case 10: run_batch<10>(aP, aQT, biasp, EPS2, out, q0, p); break;
            case 9:  run_batch<9>(aP, aQT, biasp, EPS2, out, q0, p); break;
            case 8:  run_batch<8>(aP, aQT, biasp, EPS2, out, q0, p); break;
            case 7:  run_batch<7>(aP, aQT, biasp, EPS2, out, q0, p); break;
            case 6:  run_batch<6>(aP, aQT, biasp, EPS2, out, q0, p); break;
            case 5:  run_batch<5>(aP, aQT, biasp, EPS2, out, q0, p); break;
            case 4:  run_batch<4>(aP, aQT, biasp, EPS2, out, q0, p); break;
            case 3:  run_batch<3>(aP, aQT, biasp, EPS2, out, q0, p); break;
            case 2:  run_batch<2>(aP, aQT, biasp, EPS2, out, q0, p); break;
            default: run_batch<1>(aP, aQT, biasp, EPS2, out, q0, p); break;
        }

        // protect qt against next batch's overwrite while partner still reads
        asm volatile("bar.sync %0, %1;" :: "r"(pid + 1), "r"(64) : "memory");

        q0 += jn;
        cnt -= jn;
    }
}

extern "C" void kernel_launch(void* const* d_in, const int* in_sizes, int n_in,
                              void* d_out, int out_size) {
    const float* Q      = (const float*)d_in[0];
    const float* angles = (const float*)d_in[1];
    const float* probes = (const float*)d_in[2];
    const float* qw     = (const float*)d_in[3];
    const float* qmw    = (const float*)d_in[4];
    const float* qbias  = (const float*)d_in[5];
    float* out = (float*)d_out;

    // probe table: NF*64 entries * 8 halves = 16 bytes = 4 floats each
    static_assert(OFF_QT == OFF_SH + NF * 64 * 4, "probe region");
    static_assert(OFF_QN == OFF_QT + PAIRS_PER_CTA * MAXQ * 64 * 4, "qt region");
    static_assert(SMEM_FLOATS == OFF_QN + WARPS_PER_CTA * 128, "qn region");
    static_assert(SMEM_FLOATS * sizeof(float) <= 232448, "smem cap");

    cudaFuncSetAttribute(main_kernel,
                         cudaFuncAttributeMaxDynamicSharedMemorySize,
                         SMEM_FLOATS * (int)sizeof(float));

    int sms = 148;
    cudaDeviceGetAttribute(&sms, cudaDevAttrMultiProcessorCount, 0);

    prep_kernel<<<NB, 64>>>(probes, angles, qw, qmw);
    main_kernel<<<sms, THREADS, SMEM_FLOATS * sizeof(float)>>>(Q, qbias, out);
}

// round 7
// speedup vs baseline: 1.0381x; 1.0381x over previous
#include <cuda_runtime.h>
#include <cstdint>

typedef unsigned long long u64;

#define NQ 16384
#define NB 128
#define NF 64
#define HD 128
#define EPSF 1e-8f

#define THREADS 768
#define WARPS_PER_CTA 24
#define PAIRS_PER_CTA 12
#define MAXQ 8      // q's per batch (4 jp pairs)
#define JPMAX 4

// Packed probe tables (prep output). Pair p couples b=p and b=p+64.
// g_probeA[f][p] = {P_real[p], P_real[p+64], P_imag[p], P_imag[p+64]}
// g_probeB[f][p] = {w[p],      w[p+64],      mw[p],     mw[p+64]}
__device__ float g_probeA[NF * 64 * 4];
__device__ float g_probeB[NF * 64 * 4];

// ---------- f32x2 helpers ----------
__device__ __forceinline__ u64 f2pk(float lo, float hi) {
    u64 r; asm("mov.b64 %0, {%1,%2};" : "=l"(r) : "f"(lo), "f"(hi)); return r;
}
__device__ __forceinline__ void f2upk(float& lo, float& hi, u64 v) {
    asm("mov.b64 {%0,%1}, %2;" : "=f"(lo), "=f"(hi) : "l"(v));
}
__device__ __forceinline__ u64 f2add(u64 a, u64 b) {
    u64 d; asm("add.rn.f32x2 %0, %1, %2;" : "=l"(d) : "l"(a), "l"(b)); return d;
}
__device__ __forceinline__ u64 f2fma(u64 a, u64 b, u64 c) {
    u64 d; asm("fma.rn.f32x2 %0, %1, %2, %3;" : "=l"(d) : "l"(a), "l"(b), "l"(c)); return d;
}
__device__ __forceinline__ float sqrt_apx(float x) {
    float r; asm("sqrt.approx.f32 %0, %1;" : "=f"(r) : "f"(x)); return r;
}
__device__ __forceinline__ float rcp_apx(float x) {
    float r; asm("rcp.approx.f32 %0, %1;" : "=f"(r) : "f"(x)); return r;
}
__device__ __forceinline__ uint32_t su32(const void* p) {
    uint32_t a;
    asm("{ .reg .u64 t; cvta.to.shared.u64 t, %1; cvt.u32.u64 %0, t; }"
        : "=r"(a) : "l"(p));
    return a;
}

// ---------- prep: one block per probe b, one thread per f ----------
__global__ __launch_bounds__(64)
void prep_kernel(const float* __restrict__ probes,
                 const float* __restrict__ angles,
                 const float* __restrict__ qw,
                 const float* __restrict__ qmw) {
    __shared__ float red[2];
    const int b = blockIdx.x;   // 0..127
    const int f = threadIdx.x;  // 0..63
    const int warp = f >> 5;
    const int lane = f & 31;

    float x0 = probes[b * HD + f];
    float x1 = probes[b * HD + NF + f];
    float ss = fmaf(x0, x0, x1 * x1);
#pragma unroll
    for (int o = 16; o; o >>= 1) ss += __shfl_xor_sync(0xffffffffu, ss, o);
    if (lane == 0) red[warp] = ss;
    __syncthreads();
    float inv = 1.0f / (sqrtf(red[0] + red[1]) + EPSF);

    float pr = x0 * inv;
    float pi = x1 * inv;
    float c, s;
    sincosf(angles[f], &s, &c);
    float Pr = pr * c - pi * s;
    float Pi = pr * s + pi * c;
    float xw = qw[b * NF + f];
    float sp = (xw > 20.0f) ? xw : log1pf(expf(xw));
    float w = -sp;
    float mw = qmw[b * NF + f];

    int p = b & 63;
    int hi = b >> 6;
    int base = (f * 64 + p) * 4;
    g_probeA[base + 0 + hi] = Pr;
    g_probeA[base + 2 + hi] = Pi;
    g_probeB[base + 0 + hi] = w;
    g_probeB[base + 2 + hi] = mw;
}

// ---------- SMEM layout (float offsets) ----------
#define OFF_SA  0        // probeA: 16384 floats (64KB)
#define OFF_SB  16384    // probeB: 16384 floats (64KB)
#define OFF_QTA 32768    // q-pair table A: 12 pairs * 4jp * 64f * 4 floats = 12288 (48KB)
                         //   entry: {-qr_j, -qr_j', -qi_j, -qi_j'}
#define OFF_QTM 45056    // q-pair table M: 12 pairs * 4jp * 64f * 2 floats = 6144 (24KB)
                         //   entry: {qm_j, qm_j'}
#define OFF_QN  51200    // per-warp qn scratch: 24*128 = 3072 floats (12KB)
#define SMEM_FLOATS 54272 // 217088 bytes

// Batch of JP q-pairs (2*JP q's, last possibly duplicated). Lane handles
// b-pair (p, p+64); f32x2 halves are the two q's of each jp.
template<int JP>
__device__ __forceinline__ void run_batch(uint32_t aA0, uint32_t aB0,
                                          uint32_t aQTA, uint32_t aQTM,
                                          u64 biasA, u64 biasB, u64 EPS2,
                                          float* __restrict__ out,
                                          int q0, int jn, int p) {
    u64 accA[JP], accB[JP];
#pragma unroll
    for (int jp = 0; jp < JP; jp++) { accA[jp] = biasA; accB[jp] = biasB; }

    for (int f = 0; f < NF; f++) {
        const uint32_t fo = (uint32_t)f * 1024u;
        // probe scalars for this lane's b-pair, duplicated over q halves
        float PrA, PrB, PiA, PiB, wA, wB, mwA, mwB;
        asm("ld.shared.v4.f32 {%0,%1,%2,%3}, [%4];"
            : "=f"(PrA), "=f"(PrB), "=f"(PiA), "=f"(PiB) : "r"(aA0 + fo));
        asm("ld.shared.v4.f32 {%0,%1,%2,%3}, [%4];"
            : "=f"(wA), "=f"(wB), "=f"(mwA), "=f"(mwB) : "r"(aB0 + fo));
        const u64 PrA2 = f2pk(PrA, PrA), PrB2 = f2pk(PrB, PrB);
        const u64 PiA2 = f2pk(PiA, PiA), PiB2 = f2pk(PiB, PiB);
        const u64 wA2  = f2pk(wA, wA),   wB2  = f2pk(wB, wB);
        const u64 mwA2 = f2pk(mwA, mwA), mwB2 = f2pk(mwB, mwB);

#pragma unroll
        for (int jp = 0; jp < JP; jp++) {
            u64 nqr, nqi, qm2;   // packed over the two q's of this jp
            asm("ld.shared.v2.b64 {%0,%1}, [%2];"
                : "=l"(nqr), "=l"(nqi)
                : "r"(aQTA + ((uint32_t)jp * 64u + (uint32_t)f) * 16u));
            asm("ld.shared.b64 %0, [%1];"
                : "=l"(qm2)
                : "r"(aQTM + ((uint32_t)jp * 64u + (uint32_t)f) * 8u));

            // b = p
            {
                u64 er = f2add(PrA2, nqr);
                u64 ei = f2add(PiA2, nqi);
                u64 d2 = f2fma(er, er, f2fma(ei, ei, EPS2));
                float lo, hi; f2upk(lo, hi, d2);
                u64 dist = f2pk(sqrt_apx(lo), sqrt_apx(hi));
                accA[jp] = f2fma(dist, wA2, accA[jp]);
                accA[jp] = f2fma(qm2, mwA2, accA[jp]);
            }
            // b = p + 64
            {
                u64 er = f2add(PrB2, nqr);
                u64 ei = f2add(PiB2, nqi);
                u64 d2 = f2fma(er, er, f2fma(ei, ei, EPS2));
                float lo, hi; f2upk(lo, hi, d2);
                u64 dist = f2pk(sqrt_apx(lo), sqrt_apx(hi));
                accB[jp] = f2fma(dist, wB2, accB[jp]);
                accB[jp] = f2fma(qm2, mwB2, accB[jp]);
            }
        }
    }

#pragma unroll
    for (int jp = 0; jp < JP; jp++) {
        const int j0 = 2 * jp, j1 = 2 * jp + 1;
        float a0, a1, b0, b1;
        f2upk(a0, a1, accA[jp]);
        f2upk(b0, b1, accB[jp]);
        float* r0 = out + (size_t)(q0 + j0) * NB;
        r0[p] = a0; r0[p + 64] = b0;
        if (j1 < jn) {
            float* r1 = out + (size_t)(q0 + j1) * NB;
            r1[p] = a1; r1[p + 64] = b1;
        }
    }
}

__global__ __launch_bounds__(THREADS, 1)
void main_kernel(const float* __restrict__ Q,
                 const float* __restrict__ bias,
                 float* __restrict__ out) {
    extern __shared__ float sm[];
    const int tid  = threadIdx.x;
    const int warp = tid >> 5;
    const int lane = tid & 31;
    const int pid  = warp >> 1;     // pair id 0..11
    const int h    = warp & 1;      // warp half within pair
    const int p    = lane + 32 * h; // b-pair index 0..63

    // Stage probe tables into SMEM
    {
        const float4* gA = (const float4*)g_probeA;
        const float4* gB = (const float4*)g_probeB;
        float4* sA4 = (float4*)(sm + OFF_SA);
        float4* sB4 = (float4*)(sm + OFF_SB);
        for (int i = tid; i < NF * 64; i += THREADS) {
            sA4[i] = gA[i];
            sB4[i] = gB[i];
        }
    }

    const u64 biasA = f2pk(bias[p], bias[p]);           // dup: both halves are q's
    const u64 biasB = f2pk(bias[p + 64], bias[p + 64]);
    const u64 EPS2  = f2pk(EPSF, EPSF);

    __syncthreads();

    const uint32_t sbase = su32(sm);
    const uint32_t aA0  = sbase + (uint32_t)p * 16u;
    const uint32_t aB0  = sbase + (uint32_t)OFF_SB * 4u + (uint32_t)p * 16u;
    const uint32_t aQTA = sbase + ((uint32_t)OFF_QTA + (uint32_t)pid * 1024u) * 4u;
    const uint32_t aQTM = sbase + ((uint32_t)OFF_QTM + (uint32_t)pid * 512u) * 4u;
    float* qn  = sm + OFF_QN + warp * 128;
    float* qta = sm + OFF_QTA + pid * 1024;
    float* qtm = sm + OFF_QTM + pid * 512;

    // ---- contiguous q-range per warp-pair (balanced to +/-1 q) ----
    const int npairs = gridDim.x * PAIRS_PER_CTA;
    const int gp = blockIdx.x * PAIRS_PER_CTA + pid;
    const int per = NQ / npairs;
    const int rem = NQ % npairs;
    int cnt, q0;
    if (gp < rem) { cnt = per + 1; q0 = gp * (per + 1); }
    else          { cnt = per;     q0 = rem * (per + 1) + (gp - rem) * per; }

    while (cnt > 0) {
        const int jn = (cnt > MAXQ) ? MAXQ : cnt;
        const bool odd = (jn & 1) != 0;

        // ---- batch prep: warps split q's by parity ----
        for (int j = h; j < jn; j += 2) {
            const float4* Qv = (const float4*)(Q + (size_t)(q0 + j) * HD);
            float4 v = Qv[lane];
            float ss = fmaf(v.x, v.x, fmaf(v.y, v.y, fmaf(v.z, v.z, v.w * v.w)));
#pragma unroll
            for (int o = 16; o; o >>= 1) ss += __shfl_xor_sync(0xffffffffu, ss, o);
            float inv = rcp_apx(sqrt_apx(ss) + EPSF);
            ((float4*)qn)[lane] = make_float4(v.x * inv, v.y * inv, v.z * inv, v.w * inv);
            __syncwarp();
            const int jp = j >> 1, half = j & 1;
            const bool dup = odd && (j == jn - 1);
#pragma unroll
            for (int k = 0; k < 2; k++) {
                int f = lane + k * 32;
                float qr = qn[f];
                float qi = qn[f + 64];
                float qm = sqrt_apx(fmaf(qr, qr, fmaf(qi, qi, EPSF)));
                float* qa = qta + (jp * 64 + f) * 4;
                float* qm_ = qtm + (jp * 64 + f) * 2;
                qa[half]     = -qr;
                qa[2 + half] = -qi;
                qm_[half]    = qm;
                if (dup) { qa[1] = -qr; qa[3] = -qi; qm_[1] = qm; }
            }
            __syncwarp();
        }
        // pair-scoped named barrier (ids 1..12)
        asm volatile("bar.sync %0, %1;" :: "r"(pid + 1), "r"(64) : "memory");

        switch ((jn + 1) >> 1) {
            case 4:  run_batch<4>(aA0, aB0, aQTA, aQTM, biasA, biasB, EPS2, out, q0, jn, p); break;
            case 3:  run_batch<3>(aA0, aB0, aQTA, aQTM, biasA, biasB, EPS2, out, q0, jn, p); break;
            case 2:  run_batch<2>(aA0, aB0, aQTA, aQTM, biasA, biasB, EPS2, out, q0, jn, p); break;
            default: run_batch<1>(aA0, aB0, aQTA, aQTM, biasA, biasB, EPS2, out, q0, jn, p); break;
        }

        // protect q-tables against next batch's overwrite
        asm volatile("bar.sync %0, %1;" :: "r"(pid + 1), "r"(64) : "memory");

        q0 += jn;
        cnt -= jn;
    }
}

extern "C" void kernel_launch(void* const* d_in, const int* in_sizes, int n_in,
                              void* d_out, int out_size) {
    const float* Q      = (const float*)d_in[0];
    const float* angles = (const float*)d_in[1];
    const float* probes = (const float*)d_in[2];
    const float* qw     = (const float*)d_in[3];
    const float* qmw    = (const float*)d_in[4];
    const float* qbias  = (const float*)d_in[5];
    float* out = (float*)d_out;

    static_assert(OFF_SB  == OFF_SA + NF * 64 * 4, "probeA region");
    static_assert(OFF_QTA == OFF_SB + NF * 64 * 4, "probeB region");
    static_assert(OFF_QTM == OFF_QTA + PAIRS_PER_CTA * JPMAX * 64 * 4, "qtA region");
    static_assert(OFF_QN  == OFF_QTM + PAIRS_PER_CTA * JPMAX * 64 * 2, "qtM region");
    static_assert(SMEM_FLOATS == OFF_QN + WARPS_PER_CTA * 128, "qn region");
    static_assert(SMEM_FLOATS * sizeof(float) <= 232448, "smem cap");

    cudaFuncSetAttribute(main_kernel,
                         cudaFuncAttributeMaxDynamicSharedMemorySize,
                         SMEM_FLOATS * (int)sizeof(float));

    int sms = 148;
    cudaDeviceGetAttribute(&sms, cudaDevAttrMultiProcessorCount, 0);

    prep_kernel<<<NB, 64>>>(probes, angles, qw, qmw);
    main_kernel<<<sms, THREADS, SMEM_FLOATS * sizeof(float)>>>(Q, qbias, out);
}